// round 14
// baseline (speedup 1.0000x reference)
#include <cuda_runtime.h>
#include <cuda_fp16.h>
#include <math.h>

#define N_TOK 2304
#define LOG2E 1.4426950408889634f

// Scratch (device globals: allocation-free per harness rules)
__device__ float  g_ssum[2 * 1024];            // sum of squares for q,k rows
__device__ float  g_inv[2 * 1024];             // inv L2 norms
__device__ __half g_xh[2u * 256u * 2304u];     // fp16 x
__device__ __half g_w1h[1536 * 256];           // fp16 w_qkv
__device__ __half g_w2h[256 * 512];            // fp16 w_proj
__device__ __half g_qkvh[2u * 1536u * 2304u];  // fp16 qkv, [b][ch][tok]
__device__ __half g_atth[2u * 512u * 2304u];   // fp16 attention output

// fp16 inputs, fp32 accumulator
__device__ __forceinline__ void mma_f16(float* d, const unsigned* a, const unsigned* b) {
    asm volatile(
        "mma.sync.aligned.m16n8k16.row.col.f32.f16.f16.f32 "
        "{%0,%1,%2,%3}, {%4,%5,%6,%7}, {%8,%9}, {%0,%1,%2,%3};\n"
        : "+f"(d[0]), "+f"(d[1]), "+f"(d[2]), "+f"(d[3])
        : "r"(a[0]), "r"(a[1]), "r"(a[2]), "r"(a[3]), "r"(b[0]), "r"(b[1]));
}
// fp16 inputs, fp16 accumulator (for S)
__device__ __forceinline__ void mma_f16acc(unsigned* d, const unsigned* a, const unsigned* b) {
    asm volatile(
        "mma.sync.aligned.m16n8k16.row.col.f16.f16.f16.f16 "
        "{%0,%1}, {%2,%3,%4,%5}, {%6,%7}, {%0,%1};\n"
        : "+r"(d[0]), "+r"(d[1])
        : "r"(a[0]), "r"(a[1]), "r"(a[2]), "r"(a[3]), "r"(b[0]), "r"(b[1]));
}
__device__ __forceinline__ void ldsm4(unsigned* r, unsigned addr) {
    asm volatile("ldmatrix.sync.aligned.m8n8.x4.shared.b16 {%0,%1,%2,%3}, [%4];"
                 : "=r"(r[0]), "=r"(r[1]), "=r"(r[2]), "=r"(r[3]) : "r"(addr));
}
__device__ __forceinline__ void ldsm4t(unsigned* r, unsigned addr) {
    asm volatile("ldmatrix.sync.aligned.m8n8.x4.trans.shared.b16 {%0,%1,%2,%3}, [%4];"
                 : "=r"(r[0]), "=r"(r[1]), "=r"(r[2]), "=r"(r[3]) : "r"(addr));
}
__device__ __forceinline__ unsigned ex2h2(unsigned x) {
    unsigned r;
    asm("ex2.approx.f16x2 %0, %1;" : "=r"(r) : "r"(x));
    return r;
}
__device__ __forceinline__ unsigned hmul2u(unsigned a, unsigned b) {
    unsigned r;
    asm("mul.rn.f16x2 %0, %1, %2;" : "=r"(r) : "r"(a), "r"(b));
    return r;
}
__device__ __forceinline__ void cp16(unsigned dst, const void* src) {
    asm volatile("cp.async.ca.shared.global [%0], [%1], 16;" :: "r"(dst), "l"(src));
}
#define CP_COMMIT asm volatile("cp.async.commit_group;")
#define CP_WAIT(n) asm volatile("cp.async.wait_group %0;" :: "n"(n))

// ---------------------------------------------------------------------------
__global__ void cvt_in(const float* __restrict__ x, const float* __restrict__ w1,
                       const float* __restrict__ w2, __half* __restrict__ xh,
                       __half* __restrict__ w1h, __half* __restrict__ w2h,
                       float* __restrict__ ssum) {
    int i = blockIdx.x * 256 + threadIdx.x;
    if (i < 2 * 256 * 2304) xh[i] = __float2half_rn(x[i]);
    if (i < 1536 * 256)     w1h[i] = __float2half_rn(w1[i]);
    if (i < 256 * 512)      w2h[i] = __float2half_rn(w2[i]);
    if (i < 2048)           ssum[i] = 0.f;
}

__global__ void rsqk(const float* __restrict__ ssum, float* __restrict__ inv) {
    int i = blockIdx.x * 256 + threadIdx.x;
    if (i < 2048) inv[i] = 1.f / fmaxf(sqrtf(ssum[i]), 1e-12f);
}

// ---------------------------------------------------------------------------
// fp16 qkv GEMM (proven): fp16 out + q/k sum-of-squares atomics
// ---------------------------------------------------------------------------
#define GA_STR 40
#define GB_STR 136

__global__ __launch_bounds__(256) void gemmqkv(
    const __half* __restrict__ W, const __half* __restrict__ X,
    __half* __restrict__ Yh, float* __restrict__ ssum) {
    __shared__ __half Ah[2][128 * GA_STR];
    __shared__ __half Bh[2][32 * GB_STR];

    const int tid = threadIdx.x, lane = tid & 31, w = tid >> 5;
    const int g = lane >> 2, tg = lane & 3;
    const int wm0 = (w & 3) * 32, wn0 = (w >> 2) * 64;
    const int n0 = blockIdx.x * 128;
    const int m0 = blockIdx.y * 128;
    const int b  = blockIdx.z;
    const bool doss = (m0 < 1024);
    const __half* Xb = X + (size_t)b * 256 * N_TOK;

    const unsigned sA = (unsigned)__cvta_generic_to_shared(&Ah[0][0]);
    const unsigned sB = (unsigned)__cvta_generic_to_shared(&Bh[0][0]);
    const unsigned lpA = (((lane & 7) + ((lane >> 3) & 1) * 8) * GA_STR +
                          ((lane >> 4) & 1) * 8);
    const unsigned lpB = (((lane & 7) + ((lane >> 3) & 1) * 8) * GB_STR +
                          ((lane >> 4) & 1) * 8);

    float acc[2][8][4] = {};

    auto issue = [&](int k0, int buf) {
#pragma unroll
        for (int e = tid; e < 512; e += 256) {
            int m = e >> 2, kq = e & 3;
            cp16(sA + (buf * 128 * GA_STR + m * GA_STR + kq * 8) * 2,
                 W + (size_t)(m0 + m) * 256 + k0 + kq * 8);
        }
#pragma unroll
        for (int e = tid; e < 512; e += 256) {
            int kk = e >> 4, nq = e & 15;
            cp16(sB + (buf * 32 * GB_STR + kk * GB_STR + nq * 8) * 2,
                 Xb + (size_t)(k0 + kk) * N_TOK + n0 + nq * 8);
        }
        CP_COMMIT;
    };

    issue(0, 0);
    for (int ch = 0; ch < 8; ch++) {
        int buf = ch & 1;
        if (ch + 1 < 8) { issue((ch + 1) * 32, buf ^ 1); CP_WAIT(1); }
        else            { CP_WAIT(0); }
        __syncthreads();
        const unsigned aB = sA + buf * 128 * GA_STR * 2;
        const unsigned bB = sB + buf * 32 * GB_STR * 2;
#pragma unroll
        for (int ks = 0; ks < 2; ks++) {
            unsigned a[2][4];
#pragma unroll
            for (int s = 0; s < 2; s++)
                ldsm4(a[s], aB + ((wm0 + 16 * s) * GA_STR + ks * 16 + lpA) * 2);
#pragma unroll
            for (int j = 0; j < 4; j++) {
                unsigned bb[4];
                ldsm4t(bb, bB + (ks * 16 * GB_STR + wn0 + j * 16 + lpB) * 2);
#pragma unroll
                for (int s = 0; s < 2; s++) {
                    mma_f16(acc[s][2 * j],     a[s], &bb[0]);
                    mma_f16(acc[s][2 * j + 1], a[s], &bb[2]);
                }
            }
        }
        __syncthreads();
    }
#pragma unroll
    for (int s = 0; s < 2; s++) {
        int r0 = m0 + wm0 + 16 * s + g, r1 = r0 + 8;
        float ss0 = 0.f, ss1 = 0.f;
#pragma unroll
        for (int nf = 0; nf < 8; nf++) {
            float a0 = acc[s][nf][0], a1 = acc[s][nf][1];
            float a2 = acc[s][nf][2], a3 = acc[s][nf][3];
            __half2 h0 = __floats2half2_rn(a0, a1);
            __half2 h1 = __floats2half2_rn(a2, a3);
            *(unsigned*)(Yh + (size_t)(b * 1536 + r0) * N_TOK + n0 + wn0 + nf * 8 + tg * 2) =
                *(unsigned*)&h0;
            *(unsigned*)(Yh + (size_t)(b * 1536 + r1) * N_TOK + n0 + wn0 + nf * 8 + tg * 2) =
                *(unsigned*)&h1;
            ss0 += a0 * a0 + a1 * a1;
            ss1 += a2 * a2 + a3 * a3;
        }
        if (doss) {
            ss0 += __shfl_xor_sync(0xffffffffu, ss0, 1);
            ss0 += __shfl_xor_sync(0xffffffffu, ss0, 2);
            ss1 += __shfl_xor_sync(0xffffffffu, ss1, 1);
            ss1 += __shfl_xor_sync(0xffffffffu, ss1, 2);
            if (tg == 0) {
                atomicAdd(&ssum[b * 1024 + r0], ss0);
                atomicAdd(&ssum[b * 1024 + r1], ss1);
            }
        }
    }
}

// ---------------------------------------------------------------------------
// fp16 GEMM for proj (proven)
// ---------------------------------------------------------------------------
template <int BM, int WM>
__global__ __launch_bounds__(256) void gemmh(
    const __half* __restrict__ W, const __half* __restrict__ X,
    const float* __restrict__ bias, float* __restrict__ Y, int K, int Mtot) {
    constexpr int NG = WM / 16;
    __shared__ __half Ah[2][BM * GA_STR];
    __shared__ __half Bh[2][32 * GB_STR];

    const int tid = threadIdx.x, lane = tid & 31, w = tid >> 5;
    const int g = lane >> 2, tg = lane & 3;
    const int wm0 = (w & 3) * WM, wn0 = (w >> 2) * 64;
    const int n0 = blockIdx.x * 128;
    const int m0 = blockIdx.y * BM;
    const int b  = blockIdx.z;
    const __half* Xb = X + (size_t)b * K * N_TOK;
    float* Yb = Y + (size_t)b * Mtot * N_TOK;

    const unsigned sA = (unsigned)__cvta_generic_to_shared(&Ah[0][0]);
    const unsigned sB = (unsigned)__cvta_generic_to_shared(&Bh[0][0]);
    const unsigned lpA = (((lane & 7) + ((lane >> 3) & 1) * 8) * GA_STR +
                          ((lane >> 4) & 1) * 8);
    const unsigned lpB = (((lane & 7) + ((lane >> 3) & 1) * 8) * GB_STR +
                          ((lane >> 4) & 1) * 8);

    float acc[NG][8][4] = {};

    auto issue = [&](int k0, int buf) {
#pragma unroll
        for (int e = tid; e < BM * 4; e += 256) {
            int m = e >> 2, kq = e & 3;
            cp16(sA + (buf * BM * GA_STR + m * GA_STR + kq * 8) * 2,
                 W + (size_t)(m0 + m) * K + k0 + kq * 8);
        }
#pragma unroll
        for (int e = tid; e < 512; e += 256) {
            int kk = e >> 4, nq = e & 15;
            cp16(sB + (buf * 32 * GB_STR + kk * GB_STR + nq * 8) * 2,
                 Xb + (size_t)(k0 + kk) * N_TOK + n0 + nq * 8);
        }
        CP_COMMIT;
    };

    issue(0, 0);
    const int nch = K >> 5;
    for (int ch = 0; ch < nch; ch++) {
        int buf = ch & 1;
        if (ch + 1 < nch) { issue((ch + 1) * 32, buf ^ 1); CP_WAIT(1); }
        else              { CP_WAIT(0); }
        __syncthreads();
        const unsigned aB = sA + buf * BM * GA_STR * 2;
        const unsigned bB = sB + buf * 32 * GB_STR * 2;
#pragma unroll
        for (int ks = 0; ks < 2; ks++) {
            unsigned a[NG][4];
#pragma unroll
            for (int s = 0; s < NG; s++)
                ldsm4(a[s], aB + ((wm0 + 16 * s) * GA_STR + ks * 16 + lpA) * 2);
#pragma unroll
            for (int j = 0; j < 4; j++) {
                unsigned bb[4];
                ldsm4t(bb, bB + (ks * 16 * GB_STR + wn0 + j * 16 + lpB) * 2);
#pragma unroll
                for (int s = 0; s < NG; s++) {
                    mma_f16(acc[s][2 * j],     a[s], &bb[0]);
                    mma_f16(acc[s][2 * j + 1], a[s], &bb[2]);
                }
            }
        }
        __syncthreads();
    }
#pragma unroll
    for (int s = 0; s < NG; s++) {
        int r0 = m0 + wm0 + 16 * s + g, r1 = r0 + 8;
        float bv0 = bias ? bias[r0] : 0.f;
        float bv1 = bias ? bias[r1] : 0.f;
#pragma unroll
        for (int nf = 0; nf < 8; nf++) {
            *(float2*)(Yb + (size_t)r0 * N_TOK + n0 + wn0 + nf * 8 + tg * 2) =
                make_float2(acc[s][nf][0] + bv0, acc[s][nf][1] + bv0);
            *(float2*)(Yb + (size_t)r1 * N_TOK + n0 + wn0 + nf * 8 + tg * 2) =
                make_float2(acc[s][nf][2] + bv1, acc[s][nf][3] + bv1);
        }
    }
}

// ---------------------------------------------------------------------------
// Flash attention v10: attn8 structure, but 512 threads / 16 warps x 16 rows.
// 4 warps/SMSP so softmax of one warp overlaps MMAs of the other three.
// ldmatrix everywhere keeps LSU traffic well under the crossbar cap.
// Smem halves: Q[64][264] | K[3][64][72] | V[3][64][72]  (89088 B)
// ---------------------------------------------------------------------------
#define QS_STR 264
#define KT_STR 72
#define KV_STAGE (64 * KT_STR)
#define Q_SMEM (64 * QS_STR)
#define ATTN_SMEM ((Q_SMEM + 6 * KV_STAGE) * 2)   // 89088 B

__global__ __launch_bounds__(512, 1) void attn10(
    const __half* __restrict__ qkvh, const float* __restrict__ inv,
    __half* __restrict__ out) {
    extern __shared__ __half smh[];

    const int tid = threadIdx.x, lane = tid & 31, w = tid >> 5;  // w: 0..15
    const int g = lane >> 2, tg = lane & 3;
    const int n0 = blockIdx.x * 256;
    const int i0 = w * 16;

    const __half* qb = qkvh + (size_t)(blockIdx.z * 1536 + blockIdx.y * 64) * N_TOK;
    const __half* kb = qb + (size_t)512 * N_TOK;
    const __half* vb = qb + (size_t)1024 * N_TOK;
    const float* invq = inv + blockIdx.z * 1024 + blockIdx.y * 64;
    const float* invk = invq + 512;

    const unsigned sBase = (unsigned)__cvta_generic_to_shared(smh);

    auto issueKV = [&](int t0, int buf) {
        // 512 threads: one K + one V cp16 each
        int d = tid >> 3, c = tid & 7;
        cp16(sBase + (Q_SMEM + buf * KV_STAGE + d * KT_STR + c * 8) * 2,
             kb + (size_t)d * N_TOK + t0 + c * 8);
        cp16(sBase + (Q_SMEM + (3 + buf) * KV_STAGE + d * KT_STR + c * 8) * 2,
             vb + (size_t)d * N_TOK + t0 + c * 8);
        CP_COMMIT;
    };

    // Q stage (one-time): 64 d x 256 tok
    {
#pragma unroll
        for (int e = tid; e < 2048; e += 512) {
            int d = e >> 5, c = e & 31;
            cp16(sBase + (d * QS_STR + c * 8) * 2, qb + (size_t)d * N_TOK + n0 + c * 8);
        }
        CP_COMMIT;
    }
    issueKV(0, 0);
    issueKV(64, 1);
    issueKV(128, 2);

    // Per-lane scale half2s: sc[kbk][hi] covers d = kbk*16 + 2tg (+1), +8
    unsigned sc[4][2];
#pragma unroll
    for (int kbk = 0; kbk < 4; kbk++) {
        int d0 = kbk * 16 + 2 * tg;
        __half2 s0 = __floats2half2_rn(invq[d0] * invk[d0] * LOG2E,
                                       invq[d0 + 1] * invk[d0 + 1] * LOG2E);
        __half2 s1 = __floats2half2_rn(invq[d0 + 8] * invk[d0 + 8] * LOG2E,
                                       invq[d0 + 9] * invk[d0 + 9] * LOG2E);
        sc[kbk][0] = *(unsigned*)&s0;
        sc[kbk][1] = *(unsigned*)&s1;
    }

    CP_WAIT(3);          // Q complete
    __syncthreads();

    // Hoist Q A-fragments via ldmatrix.trans, apply per-d scale (16 rows/warp)
    const int dlA = (lane & 7) + ((lane >> 4) & 1) * 8;   // bit4 -> d+8
    const int toA = ((lane >> 3) & 1) * 8;                // bit3 -> tok+8
    unsigned qa[4][4];
#pragma unroll
    for (int kbk = 0; kbk < 4; kbk++) {
        ldsm4t(qa[kbk], sBase + ((kbk * 16 + dlA) * QS_STR + i0 + toA) * 2);
        qa[kbk][0] = hmul2u(qa[kbk][0], sc[kbk][0]);
        qa[kbk][1] = hmul2u(qa[kbk][1], sc[kbk][0]);
        qa[kbk][2] = hmul2u(qa[kbk][2], sc[kbk][1]);
        qa[kbk][3] = hmul2u(qa[kbk][3], sc[kbk][1]);
    }

    const int dlB = (lane & 7) + ((lane >> 3) & 1) * 8;   // K: bit3 -> d+8
    const int toB = ((lane >> 4) & 1) * 8;                //    bit4 -> tok+8
    const unsigned lpV = (((lane & 7) + ((lane >> 4) & 1) * 8) * KT_STR +
                          ((lane >> 3) & 1) * 8) * 2;

    float O[8][4] = {};
    float l0 = 0.f, l1 = 0.f;

    for (int it = 0; it < 36; it++) {
        int buf = it % 3;
        CP_WAIT(2);
        __syncthreads();
        const unsigned kA = sBase + (Q_SMEM + buf * KV_STAGE) * 2;
        const unsigned vA = sBase + (Q_SMEM + (3 + buf) * KV_STAGE) * 2 + lpV;

        // S-phase: f16-accumulated S(16x64)
        unsigned S16[8][2];
#pragma unroll
        for (int nf = 0; nf < 8; nf++) { S16[nf][0] = 0u; S16[nf][1] = 0u; }
#pragma unroll
        for (int kbk = 0; kbk < 4; kbk++) {
            unsigned kr[4][4];
#pragma unroll
            for (int q = 0; q < 4; q++)
                ldsm4t(kr[q], kA + ((kbk * 16 + dlB) * KT_STR + q * 16 + toB) * 2);
#pragma unroll
            for (int q = 0; q < 4; q++) {
                mma_f16acc(S16[2 * q],     qa[kbk], &kr[q][0]);
                mma_f16acc(S16[2 * q + 1], qa[kbk], &kr[q][2]);
            }
        }

        // Bounded softmax: P = exp2(S) in f16x2, exact f32 l accumulation
#pragma unroll
        for (int nf = 0; nf < 8; nf++) {
            S16[nf][0] = ex2h2(S16[nf][0]);
            S16[nf][1] = ex2h2(S16[nf][1]);
        }
#pragma unroll
        for (int nf = 0; nf < 8; nf++) {
            float2 f;
            f = __half22float2(*(__half2*)&S16[nf][0]); l0 += f.x + f.y;
            f = __half22float2(*(__half2*)&S16[nf][1]); l1 += f.x + f.y;
        }

        // PV-phase: A = P (f16 S-accumulator layout == k16 A-fragment layout)
#pragma unroll
        for (int kk = 0; kk < 4; kk++) {
            unsigned vr[4][4];
#pragma unroll
            for (int q = 0; q < 4; q++)
                ldsm4(vr[q], vA + (q * 16 * KT_STR + kk * 16) * 2);
            unsigned pa[4] = {S16[2 * kk][0], S16[2 * kk][1],
                              S16[2 * kk + 1][0], S16[2 * kk + 1][1]};
#pragma unroll
            for (int q = 0; q < 4; q++) {
                mma_f16(O[2 * q],     pa, &vr[q][0]);
                mma_f16(O[2 * q + 1], pa, &vr[q][2]);
            }
        }
        __syncthreads();
        if (it + 3 < 36) issueKV((it + 3) * 64, buf);
        else             CP_COMMIT;   // keep wait arithmetic uniform
    }

    // Deferred l-reduction over the 4 tg-lanes per row
    l0 += __shfl_xor_sync(0xffffffffu, l0, 1);
    l0 += __shfl_xor_sync(0xffffffffu, l0, 2);
    l1 += __shfl_xor_sync(0xffffffffu, l1, 1);
    l1 += __shfl_xor_sync(0xffffffffu, l1, 2);
    float rl0 = 1.f / l0, rl1 = 1.f / l1;

    // Epilogue: stage d-major f32 via smem, store fp16
    float* Os = (float*)smh;   // 64 x 136 floats = 34.8 KB
    __half* ob = out + ((size_t)blockIdx.z * 512 + blockIdx.y * 64) * N_TOK;
#pragma unroll
    for (int pass = 0; pass < 2; pass++) {
        __syncthreads();
        if ((w >> 3) == pass) {
            int base = (w & 7) * 16;
            int ir0 = base + g, ir1 = base + g + 8;
#pragma unroll
            for (int nf = 0; nf < 8; nf++) {
                int d0 = nf * 8 + 2 * tg;
                Os[d0 * 136 + ir0]       = O[nf][0] * rl0;
                Os[(d0 + 1) * 136 + ir0] = O[nf][1] * rl0;
                Os[d0 * 136 + ir1]       = O[nf][2] * rl1;
                Os[(d0 + 1) * 136 + ir1] = O[nf][3] * rl1;
            }
        }
        __syncthreads();
        for (int e = tid; e < 2048; e += 512) {
            int d = e >> 5, i4 = e & 31;
            float4 t = *(const float4*)(&Os[d * 136 + i4 * 4]);
            __half2 h0 = __floats2half2_rn(t.x, t.y);
            __half2 h1 = __floats2half2_rn(t.z, t.w);
            *(uint2*)(ob + (size_t)d * N_TOK + n0 + pass * 128 + i4 * 4) =
                make_uint2(*(unsigned*)&h0, *(unsigned*)&h1);
        }
    }
}

// ---------------------------------------------------------------------------
extern "C" void kernel_launch(void* const* d_in, const int* in_sizes, int n_in,
                              void* d_out, int out_size) {
    (void)in_sizes; (void)n_in; (void)out_size;
    const float* x      = (const float*)d_in[0];
    const float* w_qkv  = (const float*)d_in[1];
    const float* w_proj = (const float*)d_in[2];
    const float* b_proj = (const float*)d_in[3];
    float* y = (float*)d_out;

    float *ssum_p, *inv_p;
    __half *xh_p, *w1h_p, *w2h_p, *qkvh_p, *atth_p;
    cudaGetSymbolAddress((void**)&ssum_p, g_ssum);
    cudaGetSymbolAddress((void**)&inv_p, g_inv);
    cudaGetSymbolAddress((void**)&xh_p, g_xh);
    cudaGetSymbolAddress((void**)&w1h_p, g_w1h);
    cudaGetSymbolAddress((void**)&w2h_p, g_w2h);
    cudaGetSymbolAddress((void**)&qkvh_p, g_qkvh);
    cudaGetSymbolAddress((void**)&atth_p, g_atth);

    cudaFuncSetAttribute(attn10, cudaFuncAttributeMaxDynamicSharedMemorySize,
                         ATTN_SMEM);

    // 0) convert inputs to fp16, zero ssum
    cvt_in<<<4608, 256>>>(x, w_qkv, w_proj, xh_p, w1h_p, w2h_p, ssum_p);
    // 1) qkv = w_qkv @ x -> fp16 qkv + q/k sum-of-squares
    gemmqkv<<<dim3(18, 12, 2), 256>>>(w1h_p, xh_p, qkvh_p, ssum_p);
    // 2) inv norms
    rsqk<<<8, 256>>>(ssum_p, inv_p);
    // 3) flash attention (16 warps x 16 rows)
    attn10<<<dim3(9, 8, 2), 512, ATTN_SMEM>>>(qkvh_p, inv_p, atth_p);
    // 4) y = w_proj @ att + b_proj
    gemmh<64, 16><<<dim3(18, 4, 2), 256>>>(w2h_p, atth_p, b_proj, y, 512, 256);
}

// round 15
// speedup vs baseline: 1.1230x; 1.1230x over previous
#include <cuda_runtime.h>
#include <cuda_fp16.h>
#include <math.h>

#define N_TOK 2304
#define LOG2E 1.4426950408889634f

// Scratch (device globals: allocation-free per harness rules)
__device__ float  g_ssum[2 * 1024];            // sum of squares for q,k rows
__device__ float  g_inv[2 * 1024];             // inv L2 norms
__device__ __half g_xh[2u * 256u * 2304u];     // fp16 x
__device__ __half g_w1h[1536 * 256];           // fp16 w_qkv
__device__ __half g_w2h[256 * 512];            // fp16 w_proj
__device__ __half g_qkvh[2u * 1536u * 2304u];  // fp16 qkv, [b][ch][tok]
__device__ __half g_atth[2u * 512u * 2304u];   // fp16 attention output

// fp16 inputs, fp32 accumulator
__device__ __forceinline__ void mma_f16(float* d, const unsigned* a, const unsigned* b) {
    asm volatile(
        "mma.sync.aligned.m16n8k16.row.col.f32.f16.f16.f32 "
        "{%0,%1,%2,%3}, {%4,%5,%6,%7}, {%8,%9}, {%0,%1,%2,%3};\n"
        : "+f"(d[0]), "+f"(d[1]), "+f"(d[2]), "+f"(d[3])
        : "r"(a[0]), "r"(a[1]), "r"(a[2]), "r"(a[3]), "r"(b[0]), "r"(b[1]));
}
// fp16 inputs, fp16 accumulator (for S)
__device__ __forceinline__ void mma_f16acc(unsigned* d, const unsigned* a, const unsigned* b) {
    asm volatile(
        "mma.sync.aligned.m16n8k16.row.col.f16.f16.f16.f16 "
        "{%0,%1}, {%2,%3,%4,%5}, {%6,%7}, {%0,%1};\n"
        : "+r"(d[0]), "+r"(d[1])
        : "r"(a[0]), "r"(a[1]), "r"(a[2]), "r"(a[3]), "r"(b[0]), "r"(b[1]));
}
__device__ __forceinline__ void ldsm4(unsigned* r, unsigned addr) {
    asm volatile("ldmatrix.sync.aligned.m8n8.x4.shared.b16 {%0,%1,%2,%3}, [%4];"
                 : "=r"(r[0]), "=r"(r[1]), "=r"(r[2]), "=r"(r[3]) : "r"(addr));
}
__device__ __forceinline__ void ldsm4t(unsigned* r, unsigned addr) {
    asm volatile("ldmatrix.sync.aligned.m8n8.x4.trans.shared.b16 {%0,%1,%2,%3}, [%4];"
                 : "=r"(r[0]), "=r"(r[1]), "=r"(r[2]), "=r"(r[3]) : "r"(addr));
}
__device__ __forceinline__ unsigned ex2h2(unsigned x) {
    unsigned r;
    asm("ex2.approx.f16x2 %0, %1;" : "=r"(r) : "r"(x));
    return r;
}
__device__ __forceinline__ unsigned hmul2u(unsigned a, unsigned b) {
    unsigned r;
    asm("mul.rn.f16x2 %0, %1, %2;" : "=r"(r) : "r"(a), "r"(b));
    return r;
}
__device__ __forceinline__ void cp16(unsigned dst, const void* src) {
    asm volatile("cp.async.ca.shared.global [%0], [%1], 16;" :: "r"(dst), "l"(src));
}
#define CP_COMMIT asm volatile("cp.async.commit_group;")
#define CP_WAIT(n) asm volatile("cp.async.wait_group %0;" :: "n"(n))

// ---------------------------------------------------------------------------
__global__ void cvt_in(const float* __restrict__ x, const float* __restrict__ w1,
                       const float* __restrict__ w2, __half* __restrict__ xh,
                       __half* __restrict__ w1h, __half* __restrict__ w2h,
                       float* __restrict__ ssum) {
    int i = blockIdx.x * 256 + threadIdx.x;
    if (i < 2 * 256 * 2304) xh[i] = __float2half_rn(x[i]);
    if (i < 1536 * 256)     w1h[i] = __float2half_rn(w1[i]);
    if (i < 256 * 512)      w2h[i] = __float2half_rn(w2[i]);
    if (i < 2048)           ssum[i] = 0.f;
}

__global__ void rsqk(const float* __restrict__ ssum, float* __restrict__ inv) {
    int i = blockIdx.x * 256 + threadIdx.x;
    if (i < 2048) inv[i] = 1.f / fmaxf(sqrtf(ssum[i]), 1e-12f);
}

// ---------------------------------------------------------------------------
// fp16 qkv GEMM (proven): fp16 out + q/k sum-of-squares atomics
// ---------------------------------------------------------------------------
#define GA_STR 40
#define GB_STR 136

__global__ __launch_bounds__(256) void gemmqkv(
    const __half* __restrict__ W, const __half* __restrict__ X,
    __half* __restrict__ Yh, float* __restrict__ ssum) {
    __shared__ __half Ah[2][128 * GA_STR];
    __shared__ __half Bh[2][32 * GB_STR];

    const int tid = threadIdx.x, lane = tid & 31, w = tid >> 5;
    const int g = lane >> 2, tg = lane & 3;
    const int wm0 = (w & 3) * 32, wn0 = (w >> 2) * 64;
    const int n0 = blockIdx.x * 128;
    const int m0 = blockIdx.y * 128;
    const int b  = blockIdx.z;
    const bool doss = (m0 < 1024);
    const __half* Xb = X + (size_t)b * 256 * N_TOK;

    const unsigned sA = (unsigned)__cvta_generic_to_shared(&Ah[0][0]);
    const unsigned sB = (unsigned)__cvta_generic_to_shared(&Bh[0][0]);
    const unsigned lpA = (((lane & 7) + ((lane >> 3) & 1) * 8) * GA_STR +
                          ((lane >> 4) & 1) * 8);
    const unsigned lpB = (((lane & 7) + ((lane >> 3) & 1) * 8) * GB_STR +
                          ((lane >> 4) & 1) * 8);

    float acc[2][8][4] = {};

    auto issue = [&](int k0, int buf) {
#pragma unroll
        for (int e = tid; e < 512; e += 256) {
            int m = e >> 2, kq = e & 3;
            cp16(sA + (buf * 128 * GA_STR + m * GA_STR + kq * 8) * 2,
                 W + (size_t)(m0 + m) * 256 + k0 + kq * 8);
        }
#pragma unroll
        for (int e = tid; e < 512; e += 256) {
            int kk = e >> 4, nq = e & 15;
            cp16(sB + (buf * 32 * GB_STR + kk * GB_STR + nq * 8) * 2,
                 Xb + (size_t)(k0 + kk) * N_TOK + n0 + nq * 8);
        }
        CP_COMMIT;
    };

    issue(0, 0);
    for (int ch = 0; ch < 8; ch++) {
        int buf = ch & 1;
        if (ch + 1 < 8) { issue((ch + 1) * 32, buf ^ 1); CP_WAIT(1); }
        else            { CP_WAIT(0); }
        __syncthreads();
        const unsigned aB = sA + buf * 128 * GA_STR * 2;
        const unsigned bB = sB + buf * 32 * GB_STR * 2;
#pragma unroll
        for (int ks = 0; ks < 2; ks++) {
            unsigned a[2][4];
#pragma unroll
            for (int s = 0; s < 2; s++)
                ldsm4(a[s], aB + ((wm0 + 16 * s) * GA_STR + ks * 16 + lpA) * 2);
#pragma unroll
            for (int j = 0; j < 4; j++) {
                unsigned bb[4];
                ldsm4t(bb, bB + (ks * 16 * GB_STR + wn0 + j * 16 + lpB) * 2);
#pragma unroll
                for (int s = 0; s < 2; s++) {
                    mma_f16(acc[s][2 * j],     a[s], &bb[0]);
                    mma_f16(acc[s][2 * j + 1], a[s], &bb[2]);
                }
            }
        }
        __syncthreads();
    }
#pragma unroll
    for (int s = 0; s < 2; s++) {
        int r0 = m0 + wm0 + 16 * s + g, r1 = r0 + 8;
        float ss0 = 0.f, ss1 = 0.f;
#pragma unroll
        for (int nf = 0; nf < 8; nf++) {
            float a0 = acc[s][nf][0], a1 = acc[s][nf][1];
            float a2 = acc[s][nf][2], a3 = acc[s][nf][3];
            __half2 h0 = __floats2half2_rn(a0, a1);
            __half2 h1 = __floats2half2_rn(a2, a3);
            *(unsigned*)(Yh + (size_t)(b * 1536 + r0) * N_TOK + n0 + wn0 + nf * 8 + tg * 2) =
                *(unsigned*)&h0;
            *(unsigned*)(Yh + (size_t)(b * 1536 + r1) * N_TOK + n0 + wn0 + nf * 8 + tg * 2) =
                *(unsigned*)&h1;
            ss0 += a0 * a0 + a1 * a1;
            ss1 += a2 * a2 + a3 * a3;
        }
        if (doss) {
            ss0 += __shfl_xor_sync(0xffffffffu, ss0, 1);
            ss0 += __shfl_xor_sync(0xffffffffu, ss0, 2);
            ss1 += __shfl_xor_sync(0xffffffffu, ss1, 1);
            ss1 += __shfl_xor_sync(0xffffffffu, ss1, 2);
            if (tg == 0) {
                atomicAdd(&ssum[b * 1024 + r0], ss0);
                atomicAdd(&ssum[b * 1024 + r1], ss1);
            }
        }
    }
}

// ---------------------------------------------------------------------------
// fp16 GEMM for proj (proven)
// ---------------------------------------------------------------------------
template <int BM, int WM>
__global__ __launch_bounds__(256) void gemmh(
    const __half* __restrict__ W, const __half* __restrict__ X,
    const float* __restrict__ bias, float* __restrict__ Y, int K, int Mtot) {
    constexpr int NG = WM / 16;
    __shared__ __half Ah[2][BM * GA_STR];
    __shared__ __half Bh[2][32 * GB_STR];

    const int tid = threadIdx.x, lane = tid & 31, w = tid >> 5;
    const int g = lane >> 2, tg = lane & 3;
    const int wm0 = (w & 3) * WM, wn0 = (w >> 2) * 64;
    const int n0 = blockIdx.x * 128;
    const int m0 = blockIdx.y * BM;
    const int b  = blockIdx.z;
    const __half* Xb = X + (size_t)b * K * N_TOK;
    float* Yb = Y + (size_t)b * Mtot * N_TOK;

    const unsigned sA = (unsigned)__cvta_generic_to_shared(&Ah[0][0]);
    const unsigned sB = (unsigned)__cvta_generic_to_shared(&Bh[0][0]);
    const unsigned lpA = (((lane & 7) + ((lane >> 3) & 1) * 8) * GA_STR +
                          ((lane >> 4) & 1) * 8);
    const unsigned lpB = (((lane & 7) + ((lane >> 3) & 1) * 8) * GB_STR +
                          ((lane >> 4) & 1) * 8);

    float acc[NG][8][4] = {};

    auto issue = [&](int k0, int buf) {
#pragma unroll
        for (int e = tid; e < BM * 4; e += 256) {
            int m = e >> 2, kq = e & 3;
            cp16(sA + (buf * BM * GA_STR + m * GA_STR + kq * 8) * 2,
                 W + (size_t)(m0 + m) * K + k0 + kq * 8);
        }
#pragma unroll
        for (int e = tid; e < 512; e += 256) {
            int kk = e >> 4, nq = e & 15;
            cp16(sB + (buf * 32 * GB_STR + kk * GB_STR + nq * 8) * 2,
                 Xb + (size_t)(k0 + kk) * N_TOK + n0 + nq * 8);
        }
        CP_COMMIT;
    };

    issue(0, 0);
    const int nch = K >> 5;
    for (int ch = 0; ch < nch; ch++) {
        int buf = ch & 1;
        if (ch + 1 < nch) { issue((ch + 1) * 32, buf ^ 1); CP_WAIT(1); }
        else              { CP_WAIT(0); }
        __syncthreads();
        const unsigned aB = sA + buf * BM * GA_STR * 2;
        const unsigned bB = sB + buf * 32 * GB_STR * 2;
#pragma unroll
        for (int ks = 0; ks < 2; ks++) {
            unsigned a[NG][4];
#pragma unroll
            for (int s = 0; s < NG; s++)
                ldsm4(a[s], aB + ((wm0 + 16 * s) * GA_STR + ks * 16 + lpA) * 2);
#pragma unroll
            for (int j = 0; j < 4; j++) {
                unsigned bb[4];
                ldsm4t(bb, bB + (ks * 16 * GB_STR + wn0 + j * 16 + lpB) * 2);
#pragma unroll
                for (int s = 0; s < NG; s++) {
                    mma_f16(acc[s][2 * j],     a[s], &bb[0]);
                    mma_f16(acc[s][2 * j + 1], a[s], &bb[2]);
                }
            }
        }
        __syncthreads();
    }
#pragma unroll
    for (int s = 0; s < NG; s++) {
        int r0 = m0 + wm0 + 16 * s + g, r1 = r0 + 8;
        float bv0 = bias ? bias[r0] : 0.f;
        float bv1 = bias ? bias[r1] : 0.f;
#pragma unroll
        for (int nf = 0; nf < 8; nf++) {
            *(float2*)(Yb + (size_t)r0 * N_TOK + n0 + wn0 + nf * 8 + tg * 2) =
                make_float2(acc[s][nf][0] + bv0, acc[s][nf][1] + bv0);
            *(float2*)(Yb + (size_t)r1 * N_TOK + n0 + wn0 + nf * 8 + tg * 2) =
                make_float2(acc[s][nf][2] + bv1, acc[s][nf][3] + bv1);
        }
    }
}

// ---------------------------------------------------------------------------
// Flash attention v11: attn8 (8 warps x 32 rows) + 4-stage KV ring +
// SINGLE barrier per tile (trailing barrier removed — write target
// (it+3)%4 != it%4, and the top-of-tile barrier bounds warp skew to one
// tile, so no reader of stage (it+4)%4 = it%4 can still be active).
// Warps drift within a tile: softmax of one overlaps MMAs of others.
// Smem halves: Q[64][264] | K[4][64][72] | V[4][64][72]  (107520 B)
// ---------------------------------------------------------------------------
#define QS_STR 264
#define KT_STR 72
#define KV_STAGE (64 * KT_STR)
#define Q_SMEM (64 * QS_STR)
#define NSTG 4
#define ATTN_SMEM ((Q_SMEM + 2 * NSTG * KV_STAGE) * 2)   // 107520 B

__global__ __launch_bounds__(256, 1) void attn11(
    const __half* __restrict__ qkvh, const float* __restrict__ inv,
    __half* __restrict__ out) {
    extern __shared__ __half smh[];

    const int tid = threadIdx.x, lane = tid & 31, w = tid >> 5;
    const int g = lane >> 2, tg = lane & 3;
    const int n0 = blockIdx.x * 256;
    const int i0 = w * 32;

    const __half* qb = qkvh + (size_t)(blockIdx.z * 1536 + blockIdx.y * 64) * N_TOK;
    const __half* kb = qb + (size_t)512 * N_TOK;
    const __half* vb = qb + (size_t)1024 * N_TOK;
    const float* invq = inv + blockIdx.z * 1024 + blockIdx.y * 64;
    const float* invk = invq + 512;

    const unsigned sBase = (unsigned)__cvta_generic_to_shared(smh);

    auto issueKV = [&](int t0, int st) {
#pragma unroll
        for (int e = tid; e < 512; e += 256) {
            int d = e >> 3, c = e & 7;
            cp16(sBase + (Q_SMEM + st * KV_STAGE + d * KT_STR + c * 8) * 2,
                 kb + (size_t)d * N_TOK + t0 + c * 8);
            cp16(sBase + (Q_SMEM + (NSTG + st) * KV_STAGE + d * KT_STR + c * 8) * 2,
                 vb + (size_t)d * N_TOK + t0 + c * 8);
        }
        CP_COMMIT;
    };

    // Q stage (one-time): 64 d x 256 tok
    {
#pragma unroll
        for (int e = tid; e < 2048; e += 256) {
            int d = e >> 5, c = e & 31;
            cp16(sBase + (d * QS_STR + c * 8) * 2, qb + (size_t)d * N_TOK + n0 + c * 8);
        }
        CP_COMMIT;
    }
    issueKV(0, 0);
    issueKV(64, 1);
    issueKV(128, 2);

    // Per-lane scale half2s: sc[kbk][hi] covers d = kbk*16 + 2tg (+1), +8
    unsigned sc[4][2];
#pragma unroll
    for (int kbk = 0; kbk < 4; kbk++) {
        int d0 = kbk * 16 + 2 * tg;
        __half2 s0 = __floats2half2_rn(invq[d0] * invk[d0] * LOG2E,
                                       invq[d0 + 1] * invk[d0 + 1] * LOG2E);
        __half2 s1 = __floats2half2_rn(invq[d0 + 8] * invk[d0 + 8] * LOG2E,
                                       invq[d0 + 9] * invk[d0 + 9] * LOG2E);
        sc[kbk][0] = *(unsigned*)&s0;
        sc[kbk][1] = *(unsigned*)&s1;
    }

    CP_WAIT(3);          // Q complete
    __syncthreads();

    // Hoist Q A-fragments via ldmatrix.trans, apply per-d scale
    const int dlA = (lane & 7) + ((lane >> 4) & 1) * 8;   // bit4 -> d+8
    const int toA = ((lane >> 3) & 1) * 8;                // bit3 -> tok+8
    unsigned qa[2][4][4];
#pragma unroll
    for (int grp = 0; grp < 2; grp++) {
#pragma unroll
        for (int kbk = 0; kbk < 4; kbk++) {
            ldsm4t(qa[grp][kbk],
                   sBase + ((kbk * 16 + dlA) * QS_STR + i0 + grp * 16 + toA) * 2);
            qa[grp][kbk][0] = hmul2u(qa[grp][kbk][0], sc[kbk][0]);
            qa[grp][kbk][1] = hmul2u(qa[grp][kbk][1], sc[kbk][0]);
            qa[grp][kbk][2] = hmul2u(qa[grp][kbk][2], sc[kbk][1]);
            qa[grp][kbk][3] = hmul2u(qa[grp][kbk][3], sc[kbk][1]);
        }
    }

    const int dlB = (lane & 7) + ((lane >> 3) & 1) * 8;   // K: bit3 -> d+8
    const int toB = ((lane >> 4) & 1) * 8;                //    bit4 -> tok+8
    const unsigned lpV = (((lane & 7) + ((lane >> 4) & 1) * 8) * KT_STR +
                          ((lane >> 3) & 1) * 8) * 2;

    float O[2][8][4] = {};
    float l00 = 0.f, l01 = 0.f, l10 = 0.f, l11 = 0.f;

    for (int it = 0; it < 36; it++) {
        int buf = it & 3;
        CP_WAIT(2);
        __syncthreads();               // the ONLY barrier per tile
        const unsigned kA = sBase + (Q_SMEM + buf * KV_STAGE) * 2;
        const unsigned vA = sBase + (Q_SMEM + (NSTG + buf) * KV_STAGE) * 2 + lpV;

        // S-phase: f16-accumulated S(32x64)
        unsigned S16[2][8][2];
#pragma unroll
        for (int grp = 0; grp < 2; grp++)
#pragma unroll
            for (int nf = 0; nf < 8; nf++) {
                S16[grp][nf][0] = 0u; S16[grp][nf][1] = 0u;
            }
#pragma unroll
        for (int kbk = 0; kbk < 4; kbk++) {
            unsigned kr[4][4];
#pragma unroll
            for (int q = 0; q < 4; q++)
                ldsm4t(kr[q], kA + ((kbk * 16 + dlB) * KT_STR + q * 16 + toB) * 2);
#pragma unroll
            for (int q = 0; q < 4; q++) {
                mma_f16acc(S16[0][2 * q],     qa[0][kbk], &kr[q][0]);
                mma_f16acc(S16[0][2 * q + 1], qa[0][kbk], &kr[q][2]);
                mma_f16acc(S16[1][2 * q],     qa[1][kbk], &kr[q][0]);
                mma_f16acc(S16[1][2 * q + 1], qa[1][kbk], &kr[q][2]);
            }
        }

        // Bounded softmax: P = exp2(S) in f16x2 (log2e pre-folded)
#pragma unroll
        for (int grp = 0; grp < 2; grp++)
#pragma unroll
            for (int nf = 0; nf < 8; nf++) {
                S16[grp][nf][0] = ex2h2(S16[grp][nf][0]);
                S16[grp][nf][1] = ex2h2(S16[grp][nf][1]);
            }

        // PV-phase first (tensor work), l-accum after (hides under drain)
#pragma unroll
        for (int kk = 0; kk < 4; kk++) {
            unsigned vr[4][4];
#pragma unroll
            for (int q = 0; q < 4; q++)
                ldsm4(vr[q], vA + (q * 16 * KT_STR + kk * 16) * 2);
            unsigned pa0[4] = {S16[0][2 * kk][0], S16[0][2 * kk][1],
                              S16[0][2 * kk + 1][0], S16[0][2 * kk + 1][1]};
            unsigned pa1[4] = {S16[1][2 * kk][0], S16[1][2 * kk][1],
                              S16[1][2 * kk + 1][0], S16[1][2 * kk + 1][1]};
#pragma unroll
            for (int q = 0; q < 4; q++) {
                mma_f16(O[0][2 * q],     pa0, &vr[q][0]);
                mma_f16(O[0][2 * q + 1], pa0, &vr[q][2]);
                mma_f16(O[1][2 * q],     pa1, &vr[q][0]);
                mma_f16(O[1][2 * q + 1], pa1, &vr[q][2]);
            }
        }

        // Deferred l-accumulation (FMA pipe, overlaps PV tensor drain)
#pragma unroll
        for (int nf = 0; nf < 8; nf++) {
            float2 f;
            f = __half22float2(*(__half2*)&S16[0][nf][0]); l00 += f.x + f.y;
            f = __half22float2(*(__half2*)&S16[0][nf][1]); l01 += f.x + f.y;
            f = __half22float2(*(__half2*)&S16[1][nf][0]); l10 += f.x + f.y;
            f = __half22float2(*(__half2*)&S16[1][nf][1]); l11 += f.x + f.y;
        }

        // NO trailing barrier: stage (it+3)&3 != buf, and top-of-tile
        // barrier bounds skew so stage (it+3)&3's old readers are done.
        if (it + 3 < 36) issueKV((it + 3) * 64, (it + 3) & 3);
        else             CP_COMMIT;   // keep wait arithmetic uniform
    }

    l00 += __shfl_xor_sync(0xffffffffu, l00, 1);
    l00 += __shfl_xor_sync(0xffffffffu, l00, 2);
    l01 += __shfl_xor_sync(0xffffffffu, l01, 1);
    l01 += __shfl_xor_sync(0xffffffffu, l01, 2);
    l10 += __shfl_xor_sync(0xffffffffu, l10, 1);
    l10 += __shfl_xor_sync(0xffffffffu, l10, 2);
    l11 += __shfl_xor_sync(0xffffffffu, l11, 1);
    l11 += __shfl_xor_sync(0xffffffffu, l11, 2);
    float rl[2][2] = {{1.f / l00, 1.f / l01}, {1.f / l10, 1.f / l11}};

    // Epilogue: stage d-major f32 via smem, store fp16
    float* Os = (float*)smh;
    __half* ob = out + ((size_t)blockIdx.z * 512 + blockIdx.y * 64) * N_TOK;
#pragma unroll
    for (int pass = 0; pass < 2; pass++) {
        __syncthreads();
        if ((w >> 2) == pass) {
            int base = (w & 3) * 32;
#pragma unroll
            for (int grp = 0; grp < 2; grp++) {
                int ir0 = base + 16 * grp + g, ir1 = ir0 + 8;
#pragma unroll
                for (int nf = 0; nf < 8; nf++) {
                    int d0 = nf * 8 + 2 * tg;
                    Os[d0 * 136 + ir0]       = O[grp][nf][0] * rl[grp][0];
                    Os[(d0 + 1) * 136 + ir0] = O[grp][nf][1] * rl[grp][0];
                    Os[d0 * 136 + ir1]       = O[grp][nf][2] * rl[grp][1];
                    Os[(d0 + 1) * 136 + ir1] = O[grp][nf][3] * rl[grp][1];
                }
            }
        }
        __syncthreads();
        for (int e = tid; e < 2048; e += 256) {
            int d = e >> 5, i4 = e & 31;
            float4 t = *(const float4*)(&Os[d * 136 + i4 * 4]);
            __half2 h0 = __floats2half2_rn(t.x, t.y);
            __half2 h1 = __floats2half2_rn(t.z, t.w);
            *(uint2*)(ob + (size_t)d * N_TOK + n0 + pass * 128 + i4 * 4) =
                make_uint2(*(unsigned*)&h0, *(unsigned*)&h1);
        }
    }
}

// ---------------------------------------------------------------------------
extern "C" void kernel_launch(void* const* d_in, const int* in_sizes, int n_in,
                              void* d_out, int out_size) {
    (void)in_sizes; (void)n_in; (void)out_size;
    const float* x      = (const float*)d_in[0];
    const float* w_qkv  = (const float*)d_in[1];
    const float* w_proj = (const float*)d_in[2];
    const float* b_proj = (const float*)d_in[3];
    float* y = (float*)d_out;

    float *ssum_p, *inv_p;
    __half *xh_p, *w1h_p, *w2h_p, *qkvh_p, *atth_p;
    cudaGetSymbolAddress((void**)&ssum_p, g_ssum);
    cudaGetSymbolAddress((void**)&inv_p, g_inv);
    cudaGetSymbolAddress((void**)&xh_p, g_xh);
    cudaGetSymbolAddress((void**)&w1h_p, g_w1h);
    cudaGetSymbolAddress((void**)&w2h_p, g_w2h);
    cudaGetSymbolAddress((void**)&qkvh_p, g_qkvh);
    cudaGetSymbolAddress((void**)&atth_p, g_atth);

    cudaFuncSetAttribute(attn11, cudaFuncAttributeMaxDynamicSharedMemorySize,
                         ATTN_SMEM);

    // 0) convert inputs to fp16, zero ssum
    cvt_in<<<4608, 256>>>(x, w_qkv, w_proj, xh_p, w1h_p, w2h_p, ssum_p);
    // 1) qkv = w_qkv @ x -> fp16 qkv + q/k sum-of-squares
    gemmqkv<<<dim3(18, 12, 2), 256>>>(w1h_p, xh_p, qkvh_p, ssum_p);
    // 2) inv norms
    rsqk<<<8, 256>>>(ssum_p, inv_p);
    // 3) flash attention (4-stage ring, single barrier per tile)
    attn11<<<dim3(9, 8, 2), 256, ATTN_SMEM>>>(qkvh_p, inv_p, atth_p);
    // 4) y = w_proj @ att + b_proj
    gemmh<64, 16><<<dim3(18, 4, 2), 256>>>(w2h_p, atth_p, b_proj, y, 512, 256);
}

// round 16
// speedup vs baseline: 1.1565x; 1.0298x over previous
#include <cuda_runtime.h>
#include <cuda_fp16.h>
#include <math.h>

#define N_TOK 2304
#define LOG2E 1.4426950408889634f

// Scratch (device globals: allocation-free per harness rules)
__device__ float  g_ssum[2 * 1024];            // sum of squares for q,k rows
__device__ __half g_xh[2u * 256u * 2304u];     // fp16 x
__device__ __half g_w1h[1536 * 256];           // fp16 w_qkv
__device__ __half g_w2h[256 * 512];            // fp16 w_proj
__device__ __half g_qkvh[2u * 1536u * 2304u];  // fp16 qkv, [b][ch][tok]
__device__ __half g_atth[2u * 512u * 2304u];   // fp16 attention output

// fp16 inputs, fp32 accumulator
__device__ __forceinline__ void mma_f16(float* d, const unsigned* a, const unsigned* b) {
    asm volatile(
        "mma.sync.aligned.m16n8k16.row.col.f32.f16.f16.f32 "
        "{%0,%1,%2,%3}, {%4,%5,%6,%7}, {%8,%9}, {%0,%1,%2,%3};\n"
        : "+f"(d[0]), "+f"(d[1]), "+f"(d[2]), "+f"(d[3])
        : "r"(a[0]), "r"(a[1]), "r"(a[2]), "r"(a[3]), "r"(b[0]), "r"(b[1]));
}
// fp16 inputs, fp16 accumulator (for S)
__device__ __forceinline__ void mma_f16acc(unsigned* d, const unsigned* a, const unsigned* b) {
    asm volatile(
        "mma.sync.aligned.m16n8k16.row.col.f16.f16.f16.f16 "
        "{%0,%1}, {%2,%3,%4,%5}, {%6,%7}, {%0,%1};\n"
        : "+r"(d[0]), "+r"(d[1])
        : "r"(a[0]), "r"(a[1]), "r"(a[2]), "r"(a[3]), "r"(b[0]), "r"(b[1]));
}
__device__ __forceinline__ void ldsm4(unsigned* r, unsigned addr) {
    asm volatile("ldmatrix.sync.aligned.m8n8.x4.shared.b16 {%0,%1,%2,%3}, [%4];"
                 : "=r"(r[0]), "=r"(r[1]), "=r"(r[2]), "=r"(r[3]) : "r"(addr));
}
__device__ __forceinline__ void ldsm4t(unsigned* r, unsigned addr) {
    asm volatile("ldmatrix.sync.aligned.m8n8.x4.trans.shared.b16 {%0,%1,%2,%3}, [%4];"
                 : "=r"(r[0]), "=r"(r[1]), "=r"(r[2]), "=r"(r[3]) : "r"(addr));
}
__device__ __forceinline__ unsigned ex2h2(unsigned x) {
    unsigned r;
    asm("ex2.approx.f16x2 %0, %1;" : "=r"(r) : "r"(x));
    return r;
}
__device__ __forceinline__ unsigned hmul2u(unsigned a, unsigned b) {
    unsigned r;
    asm("mul.rn.f16x2 %0, %1, %2;" : "=r"(r) : "r"(a), "r"(b));
    return r;
}
// exp2 on half2 via degree-6 Taylor Horner (FMA pipe; |x| <= ~1.45)
__device__ __forceinline__ unsigned exp2p(unsigned xu) {
    __half2 x = *(__half2*)&xu;
    __half2 r = __hfma2(x, __float2half2_rn(1.54035e-4f),
                        __float2half2_rn(1.333356e-3f));
    r = __hfma2(r, x, __float2half2_rn(9.618129e-3f));
    r = __hfma2(r, x, __float2half2_rn(5.550411e-2f));
    r = __hfma2(r, x, __float2half2_rn(2.402265e-1f));
    r = __hfma2(r, x, __float2half2_rn(6.931472e-1f));
    r = __hfma2(r, x, __float2half2_rn(1.0f));
    return *(unsigned*)&r;
}
__device__ __forceinline__ __half2 u2h(unsigned x) { return *(__half2*)&x; }

__device__ __forceinline__ void cp16(unsigned dst, const void* src) {
    asm volatile("cp.async.ca.shared.global [%0], [%1], 16;" :: "r"(dst), "l"(src));
}
#define CP_COMMIT asm volatile("cp.async.commit_group;")
#define CP_WAIT(n) asm volatile("cp.async.wait_group %0;" :: "n"(n))

// ---------------------------------------------------------------------------
__global__ void cvt_in(const float* __restrict__ x, const float* __restrict__ w1,
                       const float* __restrict__ w2, __half* __restrict__ xh,
                       __half* __restrict__ w1h, __half* __restrict__ w2h,
                       float* __restrict__ ssum) {
    int i = blockIdx.x * 256 + threadIdx.x;
    if (i < 2 * 256 * 2304) xh[i] = __float2half_rn(x[i]);
    if (i < 1536 * 256)     w1h[i] = __float2half_rn(w1[i]);
    if (i < 256 * 512)      w2h[i] = __float2half_rn(w2[i]);
    if (i < 2048)           ssum[i] = 0.f;
}

// ---------------------------------------------------------------------------
// fp16 qkv GEMM (proven): fp16 out + q/k sum-of-squares atomics
// ---------------------------------------------------------------------------
#define GA_STR 40
#define GB_STR 136

__global__ __launch_bounds__(256) void gemmqkv(
    const __half* __restrict__ W, const __half* __restrict__ X,
    __half* __restrict__ Yh, float* __restrict__ ssum) {
    __shared__ __half Ah[2][128 * GA_STR];
    __shared__ __half Bh[2][32 * GB_STR];

    const int tid = threadIdx.x, lane = tid & 31, w = tid >> 5;
    const int g = lane >> 2, tg = lane & 3;
    const int wm0 = (w & 3) * 32, wn0 = (w >> 2) * 64;
    const int n0 = blockIdx.x * 128;
    const int m0 = blockIdx.y * 128;
    const int b  = blockIdx.z;
    const bool doss = (m0 < 1024);
    const __half* Xb = X + (size_t)b * 256 * N_TOK;

    const unsigned sA = (unsigned)__cvta_generic_to_shared(&Ah[0][0]);
    const unsigned sB = (unsigned)__cvta_generic_to_shared(&Bh[0][0]);
    const unsigned lpA = (((lane & 7) + ((lane >> 3) & 1) * 8) * GA_STR +
                          ((lane >> 4) & 1) * 8);
    const unsigned lpB = (((lane & 7) + ((lane >> 3) & 1) * 8) * GB_STR +
                          ((lane >> 4) & 1) * 8);

    float acc[2][8][4] = {};

    auto issue = [&](int k0, int buf) {
#pragma unroll
        for (int e = tid; e < 512; e += 256) {
            int m = e >> 2, kq = e & 3;
            cp16(sA + (buf * 128 * GA_STR + m * GA_STR + kq * 8) * 2,
                 W + (size_t)(m0 + m) * 256 + k0 + kq * 8);
        }
#pragma unroll
        for (int e = tid; e < 512; e += 256) {
            int kk = e >> 4, nq = e & 15;
            cp16(sB + (buf * 32 * GB_STR + kk * GB_STR + nq * 8) * 2,
                 Xb + (size_t)(k0 + kk) * N_TOK + n0 + nq * 8);
        }
        CP_COMMIT;
    };

    issue(0, 0);
    for (int ch = 0; ch < 8; ch++) {
        int buf = ch & 1;
        if (ch + 1 < 8) { issue((ch + 1) * 32, buf ^ 1); CP_WAIT(1); }
        else            { CP_WAIT(0); }
        __syncthreads();
        const unsigned aB = sA + buf * 128 * GA_STR * 2;
        const unsigned bB = sB + buf * 32 * GB_STR * 2;
#pragma unroll
        for (int ks = 0; ks < 2; ks++) {
            unsigned a[2][4];
#pragma unroll
            for (int s = 0; s < 2; s++)
                ldsm4(a[s], aB + ((wm0 + 16 * s) * GA_STR + ks * 16 + lpA) * 2);
#pragma unroll
            for (int j = 0; j < 4; j++) {
                unsigned bb[4];
                ldsm4t(bb, bB + (ks * 16 * GB_STR + wn0 + j * 16 + lpB) * 2);
#pragma unroll
                for (int s = 0; s < 2; s++) {
                    mma_f16(acc[s][2 * j],     a[s], &bb[0]);
                    mma_f16(acc[s][2 * j + 1], a[s], &bb[2]);
                }
            }
        }
        __syncthreads();
    }
#pragma unroll
    for (int s = 0; s < 2; s++) {
        int r0 = m0 + wm0 + 16 * s + g, r1 = r0 + 8;
        float ss0 = 0.f, ss1 = 0.f;
#pragma unroll
        for (int nf = 0; nf < 8; nf++) {
            float a0 = acc[s][nf][0], a1 = acc[s][nf][1];
            float a2 = acc[s][nf][2], a3 = acc[s][nf][3];
            __half2 h0 = __floats2half2_rn(a0, a1);
            __half2 h1 = __floats2half2_rn(a2, a3);
            *(unsigned*)(Yh + (size_t)(b * 1536 + r0) * N_TOK + n0 + wn0 + nf * 8 + tg * 2) =
                *(unsigned*)&h0;
            *(unsigned*)(Yh + (size_t)(b * 1536 + r1) * N_TOK + n0 + wn0 + nf * 8 + tg * 2) =
                *(unsigned*)&h1;
            ss0 += a0 * a0 + a1 * a1;
            ss1 += a2 * a2 + a3 * a3;
        }
        if (doss) {
            ss0 += __shfl_xor_sync(0xffffffffu, ss0, 1);
            ss0 += __shfl_xor_sync(0xffffffffu, ss0, 2);
            ss1 += __shfl_xor_sync(0xffffffffu, ss1, 1);
            ss1 += __shfl_xor_sync(0xffffffffu, ss1, 2);
            if (tg == 0) {
                atomicAdd(&ssum[b * 1024 + r0], ss0);
                atomicAdd(&ssum[b * 1024 + r1], ss1);
            }
        }
    }
}

// ---------------------------------------------------------------------------
// fp16 GEMM for proj (proven)
// ---------------------------------------------------------------------------
template <int BM, int WM>
__global__ __launch_bounds__(256) void gemmh(
    const __half* __restrict__ W, const __half* __restrict__ X,
    const float* __restrict__ bias, float* __restrict__ Y, int K, int Mtot) {
    constexpr int NG = WM / 16;
    __shared__ __half Ah[2][BM * GA_STR];
    __shared__ __half Bh[2][32 * GB_STR];

    const int tid = threadIdx.x, lane = tid & 31, w = tid >> 5;
    const int g = lane >> 2, tg = lane & 3;
    const int wm0 = (w & 3) * WM, wn0 = (w >> 2) * 64;
    const int n0 = blockIdx.x * 128;
    const int m0 = blockIdx.y * BM;
    const int b  = blockIdx.z;
    const __half* Xb = X + (size_t)b * K * N_TOK;
    float* Yb = Y + (size_t)b * Mtot * N_TOK;

    const unsigned sA = (unsigned)__cvta_generic_to_shared(&Ah[0][0]);
    const unsigned sB = (unsigned)__cvta_generic_to_shared(&Bh[0][0]);
    const unsigned lpA = (((lane & 7) + ((lane >> 3) & 1) * 8) * GA_STR +
                          ((lane >> 4) & 1) * 8);
    const unsigned lpB = (((lane & 7) + ((lane >> 3) & 1) * 8) * GB_STR +
                          ((lane >> 4) & 1) * 8);

    float acc[NG][8][4] = {};

    auto issue = [&](int k0, int buf) {
#pragma unroll
        for (int e = tid; e < BM * 4; e += 256) {
            int m = e >> 2, kq = e & 3;
            cp16(sA + (buf * BM * GA_STR + m * GA_STR + kq * 8) * 2,
                 W + (size_t)(m0 + m) * K + k0 + kq * 8);
        }
#pragma unroll
        for (int e = tid; e < 512; e += 256) {
            int kk = e >> 4, nq = e & 15;
            cp16(sB + (buf * 32 * GB_STR + kk * GB_STR + nq * 8) * 2,
                 Xb + (size_t)(k0 + kk) * N_TOK + n0 + nq * 8);
        }
        CP_COMMIT;
    };

    issue(0, 0);
    const int nch = K >> 5;
    for (int ch = 0; ch < nch; ch++) {
        int buf = ch & 1;
        if (ch + 1 < nch) { issue((ch + 1) * 32, buf ^ 1); CP_WAIT(1); }
        else              { CP_WAIT(0); }
        __syncthreads();
        const unsigned aB = sA + buf * BM * GA_STR * 2;
        const unsigned bB = sB + buf * 32 * GB_STR * 2;
#pragma unroll
        for (int ks = 0; ks < 2; ks++) {
            unsigned a[NG][4];
#pragma unroll
            for (int s = 0; s < NG; s++)
                ldsm4(a[s], aB + ((wm0 + 16 * s) * GA_STR + ks * 16 + lpA) * 2);
#pragma unroll
            for (int j = 0; j < 4; j++) {
                unsigned bb[4];
                ldsm4t(bb, bB + (ks * 16 * GB_STR + wn0 + j * 16 + lpB) * 2);
#pragma unroll
                for (int s = 0; s < NG; s++) {
                    mma_f16(acc[s][2 * j],     a[s], &bb[0]);
                    mma_f16(acc[s][2 * j + 1], a[s], &bb[2]);
                }
            }
        }
        __syncthreads();
    }
#pragma unroll
    for (int s = 0; s < NG; s++) {
        int r0 = m0 + wm0 + 16 * s + g, r1 = r0 + 8;
        float bv0 = bias ? bias[r0] : 0.f;
        float bv1 = bias ? bias[r1] : 0.f;
#pragma unroll
        for (int nf = 0; nf < 8; nf++) {
            *(float2*)(Yb + (size_t)r0 * N_TOK + n0 + wn0 + nf * 8 + tg * 2) =
                make_float2(acc[s][nf][0] + bv0, acc[s][nf][1] + bv0);
            *(float2*)(Yb + (size_t)r1 * N_TOK + n0 + wn0 + nf * 8 + tg * 2) =
                make_float2(acc[s][nf][2] + bv1, acc[s][nf][3] + bv1);
        }
    }
}

// ---------------------------------------------------------------------------
// Flash attention v12: attn11 + pipe-balanced exp (24 ex2h2 on MUFU + 8
// poly-exp2 on FMA per warp-tile), HADD2-tree l-reduction, inlined inv-norm
// (rsqk kernel folded into prologue).
// Smem halves: Q[64][264] | K[4][64][72] | V[4][64][72] | inv[128 floats]
// ---------------------------------------------------------------------------
#define QS_STR 264
#define KT_STR 72
#define KV_STAGE (64 * KT_STR)
#define Q_SMEM (64 * QS_STR)
#define NSTG 4
#define INV_OFF (Q_SMEM + 2 * NSTG * KV_STAGE)          // halves
#define ATTN_SMEM ((INV_OFF + 256) * 2)                 // 108032 B

__global__ __launch_bounds__(256, 1) void attn12(
    const __half* __restrict__ qkvh, const float* __restrict__ ssum,
    __half* __restrict__ out) {
    extern __shared__ __half smh[];
    float* invSm = (float*)(smh + INV_OFF);   // [0..63] q, [64..127] k

    const int tid = threadIdx.x, lane = tid & 31, w = tid >> 5;
    const int g = lane >> 2, tg = lane & 3;
    const int n0 = blockIdx.x * 256;
    const int i0 = w * 32;

    const __half* qb = qkvh + (size_t)(blockIdx.z * 1536 + blockIdx.y * 64) * N_TOK;
    const __half* kb = qb + (size_t)512 * N_TOK;
    const __half* vb = qb + (size_t)1024 * N_TOK;

    const unsigned sBase = (unsigned)__cvta_generic_to_shared(smh);

    auto issueKV = [&](int t0, int st) {
#pragma unroll
        for (int e = tid; e < 512; e += 256) {
            int d = e >> 3, c = e & 7;
            cp16(sBase + (Q_SMEM + st * KV_STAGE + d * KT_STR + c * 8) * 2,
                 kb + (size_t)d * N_TOK + t0 + c * 8);
            cp16(sBase + (Q_SMEM + (NSTG + st) * KV_STAGE + d * KT_STR + c * 8) * 2,
                 vb + (size_t)d * N_TOK + t0 + c * 8);
        }
        CP_COMMIT;
    };

    // Q stage (one-time): 64 d x 256 tok
    {
#pragma unroll
        for (int e = tid; e < 2048; e += 256) {
            int d = e >> 5, c = e & 31;
            cp16(sBase + (d * QS_STR + c * 8) * 2, qb + (size_t)d * N_TOK + n0 + c * 8);
        }
        CP_COMMIT;
    }
    issueKV(0, 0);
    issueKV(64, 1);
    issueKV(128, 2);

    // Inline inv-norm computation (was rsqk kernel): 128 threads
    if (tid < 128) {
        int idx = blockIdx.z * 1024 + blockIdx.y * 64 +
                  (tid < 64 ? tid : tid + 448);   // q rows, then k rows (+512-64)
        invSm[tid] = rsqrtf(fmaxf(ssum[idx], 1e-24f));
    }

    CP_WAIT(3);          // Q complete
    __syncthreads();     // also publishes invSm

    // Per-lane scale half2s from smem inv
    unsigned sc[4][2];
#pragma unroll
    for (int kbk = 0; kbk < 4; kbk++) {
        int d0 = kbk * 16 + 2 * tg;
        __half2 s0 = __floats2half2_rn(invSm[d0] * invSm[64 + d0] * LOG2E,
                                       invSm[d0 + 1] * invSm[64 + d0 + 1] * LOG2E);
        __half2 s1 = __floats2half2_rn(invSm[d0 + 8] * invSm[64 + d0 + 8] * LOG2E,
                                       invSm[d0 + 9] * invSm[64 + d0 + 9] * LOG2E);
        sc[kbk][0] = *(unsigned*)&s0;
        sc[kbk][1] = *(unsigned*)&s1;
    }

    // Hoist Q A-fragments via ldmatrix.trans, apply per-d scale
    const int dlA = (lane & 7) + ((lane >> 4) & 1) * 8;
    const int toA = ((lane >> 3) & 1) * 8;
    unsigned qa[2][4][4];
#pragma unroll
    for (int grp = 0; grp < 2; grp++) {
#pragma unroll
        for (int kbk = 0; kbk < 4; kbk++) {
            ldsm4t(qa[grp][kbk],
                   sBase + ((kbk * 16 + dlA) * QS_STR + i0 + grp * 16 + toA) * 2);
            qa[grp][kbk][0] = hmul2u(qa[grp][kbk][0], sc[kbk][0]);
            qa[grp][kbk][1] = hmul2u(qa[grp][kbk][1], sc[kbk][0]);
            qa[grp][kbk][2] = hmul2u(qa[grp][kbk][2], sc[kbk][1]);
            qa[grp][kbk][3] = hmul2u(qa[grp][kbk][3], sc[kbk][1]);
        }
    }

    const int dlB = (lane & 7) + ((lane >> 3) & 1) * 8;
    const int toB = ((lane >> 4) & 1) * 8;
    const unsigned lpV = (((lane & 7) + ((lane >> 4) & 1) * 8) * KT_STR +
                          ((lane >> 3) & 1) * 8) * 2;

    float O[2][8][4] = {};
    float l00 = 0.f, l01 = 0.f, l10 = 0.f, l11 = 0.f;

    for (int it = 0; it < 36; it++) {
        int buf = it & 3;
        CP_WAIT(2);
        __syncthreads();               // the ONLY barrier per tile
        const unsigned kA = sBase + (Q_SMEM + buf * KV_STAGE) * 2;
        const unsigned vA = sBase + (Q_SMEM + (NSTG + buf) * KV_STAGE) * 2 + lpV;

        // S-phase: f16-accumulated S(32x64)
        unsigned S16[2][8][2];
#pragma unroll
        for (int grp = 0; grp < 2; grp++)
#pragma unroll
            for (int nf = 0; nf < 8; nf++) {
                S16[grp][nf][0] = 0u; S16[grp][nf][1] = 0u;
            }
#pragma unroll
        for (int kbk = 0; kbk < 4; kbk++) {
            unsigned kr[4][4];
#pragma unroll
            for (int q = 0; q < 4; q++)
                ldsm4t(kr[q], kA + ((kbk * 16 + dlB) * KT_STR + q * 16 + toB) * 2);
#pragma unroll
            for (int q = 0; q < 4; q++) {
                mma_f16acc(S16[0][2 * q],     qa[0][kbk], &kr[q][0]);
                mma_f16acc(S16[0][2 * q + 1], qa[0][kbk], &kr[q][2]);
                mma_f16acc(S16[1][2 * q],     qa[1][kbk], &kr[q][0]);
                mma_f16acc(S16[1][2 * q + 1], qa[1][kbk], &kr[q][2]);
            }
        }

        // Bounded softmax: pipe-balanced exp2 (MUFU for 24 regs, FMA poly for 8)
#pragma unroll
        for (int grp = 0; grp < 2; grp++)
#pragma unroll
            for (int nf = 0; nf < 8; nf++) {
                if (grp == 1 && nf >= 4) {
                    S16[grp][nf][0] = exp2p(S16[grp][nf][0]);
                    S16[grp][nf][1] = exp2p(S16[grp][nf][1]);
                } else {
                    S16[grp][nf][0] = ex2h2(S16[grp][nf][0]);
                    S16[grp][nf][1] = ex2h2(S16[grp][nf][1]);
                }
            }

        // PV-phase first (tensor work)
#pragma unroll
        for (int kk = 0; kk < 4; kk++) {
            unsigned vr[4][4];
#pragma unroll
            for (int q = 0; q < 4; q++)
                ldsm4(vr[q], vA + (q * 16 * KT_STR + kk * 16) * 2);
            unsigned pa0[4] = {S16[0][2 * kk][0], S16[0][2 * kk][1],
                              S16[0][2 * kk + 1][0], S16[0][2 * kk + 1][1]};
            unsigned pa1[4] = {S16[1][2 * kk][0], S16[1][2 * kk][1],
                              S16[1][2 * kk + 1][0], S16[1][2 * kk + 1][1]};
#pragma unroll
            for (int q = 0; q < 4; q++) {
                mma_f16(O[0][2 * q],     pa0, &vr[q][0]);
                mma_f16(O[0][2 * q + 1], pa0, &vr[q][2]);
                mma_f16(O[1][2 * q],     pa1, &vr[q][0]);
                mma_f16(O[1][2 * q + 1], pa1, &vr[q][2]);
            }
        }

        // Deferred l-accumulation via HADD2 tree (8 P values <= 22, f16-safe)
#pragma unroll
        for (int grp = 0; grp < 2; grp++) {
#pragma unroll
            for (int i = 0; i < 2; i++) {
                __half2 a0 = __hadd2(u2h(S16[grp][0][i]), u2h(S16[grp][1][i]));
                __half2 a1 = __hadd2(u2h(S16[grp][2][i]), u2h(S16[grp][3][i]));
                __half2 a2 = __hadd2(u2h(S16[grp][4][i]), u2h(S16[grp][5][i]));
                __half2 a3 = __hadd2(u2h(S16[grp][6][i]), u2h(S16[grp][7][i]));
                __half2 s = __hadd2(__hadd2(a0, a1), __hadd2(a2, a3));
                float2 f = __half22float2(s);
                float add = f.x + f.y;
                if (grp == 0) { if (i == 0) l00 += add; else l01 += add; }
                else          { if (i == 0) l10 += add; else l11 += add; }
            }
        }

        // NO trailing barrier (4-stage ring, skew bounded by top barrier)
        if (it + 3 < 36) issueKV((it + 3) * 64, (it + 3) & 3);
        else             CP_COMMIT;   // keep wait arithmetic uniform
    }

    l00 += __shfl_xor_sync(0xffffffffu, l00, 1);
    l00 += __shfl_xor_sync(0xffffffffu, l00, 2);
    l01 += __shfl_xor_sync(0xffffffffu, l01, 1);
    l01 += __shfl_xor_sync(0xffffffffu, l01, 2);
    l10 += __shfl_xor_sync(0xffffffffu, l10, 1);
    l10 += __shfl_xor_sync(0xffffffffu, l10, 2);
    l11 += __shfl_xor_sync(0xffffffffu, l11, 1);
    l11 += __shfl_xor_sync(0xffffffffu, l11, 2);
    float rl[2][2] = {{1.f / l00, 1.f / l01}, {1.f / l10, 1.f / l11}};

    // Epilogue: stage d-major f32 via smem, store fp16
    float* Os = (float*)smh;
    __half* ob = out + ((size_t)blockIdx.z * 512 + blockIdx.y * 64) * N_TOK;
#pragma unroll
    for (int pass = 0; pass < 2; pass++) {
        __syncthreads();
        if ((w >> 2) == pass) {
            int base = (w & 3) * 32;
#pragma unroll
            for (int grp = 0; grp < 2; grp++) {
                int ir0 = base + 16 * grp + g, ir1 = ir0 + 8;
#pragma unroll
                for (int nf = 0; nf < 8; nf++) {
                    int d0 = nf * 8 + 2 * tg;
                    Os[d0 * 136 + ir0]       = O[grp][nf][0] * rl[grp][0];
                    Os[(d0 + 1) * 136 + ir0] = O[grp][nf][1] * rl[grp][0];
                    Os[d0 * 136 + ir1]       = O[grp][nf][2] * rl[grp][1];
                    Os[(d0 + 1) * 136 + ir1] = O[grp][nf][3] * rl[grp][1];
                }
            }
        }
        __syncthreads();
        for (int e = tid; e < 2048; e += 256) {
            int d = e >> 5, i4 = e & 31;
            float4 t = *(const float4*)(&Os[d * 136 + i4 * 4]);
            __half2 h0 = __floats2half2_rn(t.x, t.y);
            __half2 h1 = __floats2half2_rn(t.z, t.w);
            *(uint2*)(ob + (size_t)d * N_TOK + n0 + pass * 128 + i4 * 4) =
                make_uint2(*(unsigned*)&h0, *(unsigned*)&h1);
        }
    }
}

// ---------------------------------------------------------------------------
extern "C" void kernel_launch(void* const* d_in, const int* in_sizes, int n_in,
                              void* d_out, int out_size) {
    (void)in_sizes; (void)n_in; (void)out_size;
    const float* x      = (const float*)d_in[0];
    const float* w_qkv  = (const float*)d_in[1];
    const float* w_proj = (const float*)d_in[2];
    const float* b_proj = (const float*)d_in[3];
    float* y = (float*)d_out;

    float *ssum_p;
    __half *xh_p, *w1h_p, *w2h_p, *qkvh_p, *atth_p;
    cudaGetSymbolAddress((void**)&ssum_p, g_ssum);
    cudaGetSymbolAddress((void**)&xh_p, g_xh);
    cudaGetSymbolAddress((void**)&w1h_p, g_w1h);
    cudaGetSymbolAddress((void**)&w2h_p, g_w2h);
    cudaGetSymbolAddress((void**)&qkvh_p, g_qkvh);
    cudaGetSymbolAddress((void**)&atth_p, g_atth);

    cudaFuncSetAttribute(attn12, cudaFuncAttributeMaxDynamicSharedMemorySize,
                         ATTN_SMEM);

    // 0) convert inputs to fp16, zero ssum
    cvt_in<<<4608, 256>>>(x, w_qkv, w_proj, xh_p, w1h_p, w2h_p, ssum_p);
    // 1) qkv = w_qkv @ x -> fp16 qkv + q/k sum-of-squares
    gemmqkv<<<dim3(18, 12, 2), 256>>>(w1h_p, xh_p, qkvh_p, ssum_p);
    // 2) flash attention (inv-norm inlined, pipe-balanced softmax)
    attn12<<<dim3(9, 8, 2), 256, ATTN_SMEM>>>(qkvh_p, ssum_p, atth_p);
    // 3) y = w_proj @ att + b_proj
    gemmh<64, 16><<<dim3(18, 4, 2), 256>>>(w2h_p, atth_p, b_proj, y, 512, 256);
}